// round 3
// baseline (speedup 1.0000x reference)
#include <cuda_runtime.h>

// PBKDF2-toy, fully serial: single thread, all state in registers, unrolled.
// rel_err==1.0 exactly on two logic-independent attempts => harness dtype is
// float32 (int writes reinterpret as denormals ~ 0). Output written as float;
// inputs dtype-sniffed per element (int in [0,255] kept, else bits->float).

__device__ __forceinline__ int load_byte(const void* p, int i) {
    int v = ((const int*)p)[i];
    if ((unsigned)v <= 255u) return v;            // int32 input
    float f = __int_as_float(v);                  // float32 input
    return (int)f;
}

template <int MSGLEN>
__device__ __forceinline__ void simple_hmac(const int key[16], const int* msg, int r[32]) {
    #pragma unroll
    for (int i = 0; i < 32; i++) r[i] = 0;
    // absorb: combined = key(16) ++ msg(MSGLEN), idx = i % 32
    #pragma unroll
    for (int i = 0; i < 16; i++) {
        r[i] = (r[i] * 31 + key[i]) & 255;
    }
    #pragma unroll
    for (int i = 0; i < MSGLEN; i++) {
        int j = (16 + i) & 31;
        r[j] = (r[j] * 31 + msg[i]) & 255;
    }
    // mix: 4 rounds x 32 sequential in-place updates
    #pragma unroll
    for (int rd = 0; rd < 4; rd++) {
        #pragma unroll
        for (int i = 0; i < 32; i++) {
            r[i] = (r[i] ^ (r[(i + 17) & 31] + r[(i + 11) & 31])) & 255;
        }
    }
}

__global__ void __launch_bounds__(32, 1)
Model_62955630625117_kernel(const void* __restrict__ pw_in,
                            const void* __restrict__ salt_in,
                            float* __restrict__ out) {
    if (threadIdx.x != 0) return;

    int key[16], msg0[20];
    #pragma unroll
    for (int j = 0; j < 16; j++) key[j] = load_byte(pw_in, j);
    #pragma unroll
    for (int j = 0; j < 16; j++) msg0[j] = load_byte(salt_in, j);
    msg0[16] = 0; msg0[17] = 0; msg0[18] = 0; msg0[19] = 1;  // block_num (block_idx+1 = 1)

    int U[32], nr[32], F[32];

    // U0 = hmac(password, salt ++ block_num)
    simple_hmac<20>(key, msg0, U);
    #pragma unroll
    for (int j = 0; j < 32; j++) F[j] = U[j];

    // 999 chained iterations: U = hmac(password, U); F ^= U
    #pragma unroll 1
    for (int it = 1; it < 1000; it++) {
        simple_hmac<32>(key, U, nr);
        #pragma unroll
        for (int j = 0; j < 32; j++) {
            U[j] = nr[j];
            F[j] ^= nr[j];
        }
    }

    #pragma unroll
    for (int j = 0; j < 32; j++) out[j] = (float)F[j];
}

extern "C" void kernel_launch(void* const* d_in, const int* in_sizes, int n_in,
                              void* d_out, int out_size) {
    const void* password = d_in[0];
    const void* salt     = (n_in >= 2) ? d_in[1] : (const void*)((const int*)d_in[0] + 16);
    float* out           = (float*)d_out;
    Model_62955630625117_kernel<<<1, 32>>>(password, salt, out);
}

// round 4
// speedup vs baseline: 1.1324x; 1.1324x over previous
#include <cuda_runtime.h>

// PBKDF2-toy, fully serial single-warp kernel driven toward the two-pipe
// issue floor (~320 cyc/iter: 160 LOP3 on alu-pipe, ~146 adds as IMAD on
// fma-pipe). Absorb collapsed to 16 adds + role swap (mod-256 deferred to
// the mix LOP3's fused mask); main loop unrolled x2 so the swap permutation
// is absorbed into register allocation (no MOVs); F accumulated in place.
// Harness dtype shims: float32 out, dtype-sniffed in (proven in R3).

__device__ __forceinline__ int load_byte(const void* p, int i) {
    int v = ((const int*)p)[i];
    if ((unsigned)v <= 255u) return v;            // int32 input
    return (int)__int_as_float(v);                // float32 input
}

// mix: 4 rounds x 32 sequential in-place updates, fully unrolled.
__device__ __forceinline__ void mix(unsigned r[32]) {
    #pragma unroll
    for (int rd = 0; rd < 4; rd++) {
        #pragma unroll
        for (int i = 0; i < 32; i++) {
            // (r ^ (a+b)) & 255 -> single LOP3 with imm mask; add -> IMAD/IADD3.
            r[i] = (r[i] ^ (r[(i + 17) & 31] + r[(i + 11) & 31])) & 255u;
        }
    }
}

__global__ void __launch_bounds__(32, 1)
Model_62955630625117_kernel(const void* __restrict__ pw_in,
                            const void* __restrict__ salt_in,
                            float* __restrict__ out) {
    if (threadIdx.x != 0) return;

    unsigned c[16];   // (pw[j]*31) & 255, loop-invariant key contribution
    unsigned r[32];   // hash state U (bytes; transiently 9-bit post-absorb, safe)
    unsigned F[32];   // xor accumulator

    #pragma unroll
    for (int j = 0; j < 16; j++) {
        unsigned p = (unsigned)load_byte(pw_in, j);
        c[j] = (p * 31u) & 255u;
        r[j] = p;                         // absorb touch 1 (key), zero state
    }
    #pragma unroll
    for (int j = 0; j < 16; j++) r[16 + j] = (unsigned)load_byte(salt_in, j);

    // First hmac message = salt(16) ++ block_num{0,0,0,1}:
    // positions 0..3 get second touch: r[j] = (pw[j]*31 + bn[j]) & 255.
    r[0] = c[0];
    r[1] = c[1];
    r[2] = c[2];
    r[3] = (c[3] + 1u) & 255u;
    // positions 4..15 stay pw[j]; 16..31 stay salt.

    mix(r);                               // U0
    #pragma unroll
    for (int j = 0; j < 32; j++) F[j] = r[j];

    // 999 chained iterations: U = hmac(pw, U); F ^= U.
    // Absorb collapse: new r[j] = c[j] + old r[16+j]  (j<16, mask deferred),
    //                  new r[16+j] = old r[j]         (swap).
    // Unroll 2: swap o swap = identity -> ptxas renames away all MOVs.
    #pragma unroll 2
    for (int it = 1; it < 1000; it++) {
        #pragma unroll
        for (int j = 0; j < 16; j++) {
            unsigned t = r[j];
            r[j] = c[j] + r[16 + j];      // 9-bit OK: mix LOP3 re-masks
            r[16 + j] = t;
        }
        mix(r);
        #pragma unroll
        for (int j = 0; j < 32; j++) F[j] ^= r[j];
    }

    #pragma unroll
    for (int j = 0; j < 32; j++) out[j] = (float)F[j];
}

extern "C" void kernel_launch(void* const* d_in, const int* in_sizes, int n_in,
                              void* d_out, int out_size) {
    const void* password = d_in[0];
    const void* salt     = (n_in >= 2) ? d_in[1] : (const void*)((const int*)d_in[0] + 16);
    float* out           = (float*)d_out;
    Model_62955630625117_kernel<<<1, 32>>>(password, salt, out);
}

// round 5
// speedup vs baseline: 1.1441x; 1.0104x over previous
#include <cuda_runtime.h>

// PBKDF2-toy, serial single-warp kernel at ~90% of the alu-pipe issue floor
// (160 LOP3/iter x rt2 = 320 cyc/iter). This round: (1) fully convergent
// warp-uniform execution (no early return) to enable ptxas uniform-pipe
// (UIADD3/ULOP3) offload, relaxing the alu-pipe bind toward the total-issue
// floor; (2) unroll 4 (absorb swap is order-2, registers stay stable);
// (3) F-xor fused into mix round 4 to fill iteration-boundary latency.
// Harness dtype shims: float32 out, dtype-sniffed in (proven R3).

__device__ __forceinline__ unsigned load_byte(const void* p, int i) {
    int v = ((const int*)p)[i];
    if ((unsigned)v <= 255u) return (unsigned)v;   // int32 input
    return (unsigned)(int)__int_as_float(v);       // float32 input
}

__global__ void __launch_bounds__(32, 1)
Model_62955630625117_kernel(const void* __restrict__ pw_in,
                            const void* __restrict__ salt_in,
                            float* __restrict__ out) {
    // All 32 lanes execute identically (convergent, warp-uniform) so ptxas
    // can promote the scalar chain to the uniform datapath.
    unsigned c[16];   // (pw[j]*31) & 255, loop-invariant key contribution
    unsigned r[32];   // hash state U
    unsigned F[32];   // xor accumulator

    #pragma unroll
    for (int j = 0; j < 16; j++) {
        unsigned p = load_byte(pw_in, j);
        c[j] = (p * 31u) & 255u;
        r[j] = p;
    }
    #pragma unroll
    for (int j = 0; j < 16; j++) r[16 + j] = load_byte(salt_in, j);

    // First hmac message = salt(16) ++ block_num{0,0,0,1}: second absorb
    // touch on positions 0..3 only.
    r[0] = c[0];
    r[1] = c[1];
    r[2] = c[2];
    r[3] = (c[3] + 1u) & 255u;

    // U0 mix: rounds 0-2, then round 3 fused with F init.
    #pragma unroll
    for (int rd = 0; rd < 3; rd++) {
        #pragma unroll
        for (int i = 0; i < 32; i++)
            r[i] = (r[i] ^ (r[(i + 17) & 31] + r[(i + 11) & 31])) & 255u;
    }
    #pragma unroll
    for (int i = 0; i < 32; i++) {
        r[i] = (r[i] ^ (r[(i + 17) & 31] + r[(i + 11) & 31])) & 255u;
        F[i] = r[i];
    }

    // 999 chained iterations: U = hmac(pw, U); F ^= U.
    // Absorb collapse: r[j] = c[j] + r[16+j] (9-bit OK, mix LOP3 re-masks),
    // r[16+j] = old r[j] (swap; even unroll -> pure register renaming).
    #pragma unroll 4
    for (int it = 1; it < 1000; it++) {
        #pragma unroll
        for (int j = 0; j < 16; j++) {
            unsigned t = r[j];
            r[j] = c[j] + r[16 + j];
            r[16 + j] = t;
        }
        #pragma unroll
        for (int rd = 0; rd < 3; rd++) {
            #pragma unroll
            for (int i = 0; i < 32; i++)
                r[i] = (r[i] ^ (r[(i + 17) & 31] + r[(i + 11) & 31])) & 255u;
        }
        // round 4 fused with F accumulation
        #pragma unroll
        for (int i = 0; i < 32; i++) {
            r[i] = (r[i] ^ (r[(i + 17) & 31] + r[(i + 11) & 31])) & 255u;
            F[i] ^= r[i];
        }
    }

    if (threadIdx.x == 0) {
        #pragma unroll
        for (int j = 0; j < 32; j++) out[j] = (float)F[j];
    }
}

extern "C" void kernel_launch(void* const* d_in, const int* in_sizes, int n_in,
                              void* d_out, int out_size) {
    const void* password = d_in[0];
    const void* salt     = (n_in >= 2) ? d_in[1] : (const void*)((const int*)d_in[0] + 16);
    float* out           = (float*)d_out;
    Model_62955630625117_kernel<<<1, 32>>>(password, salt, out);
}